// round 2
// baseline (speedup 1.0000x reference)
#include <cuda_runtime.h>

#define BATCH 32768
#define EMB   2048
#define FEAT  320
#define KACT  103        // ceil(0.05 * 2048)
#define BM    16

// scratch (no allocations allowed -> __device__ globals)
__device__ float g_h[BATCH * FEAT];     // pooled features, 42 MB
__device__ float g_wT[FEAT * EMB];      // fc_w transposed, 2.6 MB (L2-resident)

typedef unsigned long long ull;

__device__ __forceinline__ ull pack2(float x, float y) {
    ull r; asm("mov.b64 %0, {%1, %2};" : "=l"(r) : "f"(x), "f"(y)); return r;
}
__device__ __forceinline__ void unpack2(ull v, float& x, float& y) {
    asm("mov.b64 {%0, %1}, %2;" : "=f"(x), "=f"(y) : "l"(v));
}
// packed dual-fp32 FMA (Blackwell f32x2 pipe: 2x scalar FFMA throughput)
__device__ __forceinline__ void fma2(ull& acc, ull a, ull b) {
    asm("fma.rn.f32x2 %0, %1, %2, %0;" : "+l"(acc) : "l"(a), "l"(b));
}

// ---------------- kernel 1: transpose fc_w -> g_wT ----------------
__global__ __launch_bounds__(256) void transpose_w_kernel(const float* __restrict__ fc_w) {
    int idx = blockIdx.x * 256 + threadIdx.x;
    if (idx < FEAT * EMB) {
        int k = idx / EMB, j = idx - k * EMB;
        g_wT[idx] = fc_w[j * FEAT + k];   // coalesced store
    }
}

// ---------------- kernel 2: conv + bn + relu + maxpool ----------------
__global__ __launch_bounds__(320) void conv_pool_kernel(
    const float* __restrict__ x, const float* __restrict__ conv_w,
    const float* __restrict__ gamma, const float* __restrict__ beta,
    const float* __restrict__ mean, const float* __restrict__ var)
{
    __shared__ float img[784];
    int b = blockIdx.x;
    const float* xb = x + (size_t)b * 784;
    for (int i = threadIdx.x; i < 784; i += 320) img[i] = xb[i];

    int t = threadIdx.x;                // 320 threads = 320 pooled outputs
    int c = t >> 6, r = t & 63, py = r >> 3, px = r & 7;
    float w[9];
#pragma unroll
    for (int i = 0; i < 9; i++) w[i] = __ldg(&conv_w[c * 9 + i]);
    float s  = __ldg(&gamma[c]) / sqrtf(__ldg(&var[c]) + 1e-5f);
    float bb = __ldg(&beta[c]) - __ldg(&mean[c]) * s;
    __syncthreads();

    int y0 = py * 3, x0 = px * 3;
    float m = -3.402823466e38f;
#pragma unroll
    for (int dy = 0; dy < 3; dy++)
#pragma unroll
    for (int dx = 0; dx < 3; dx++) {
        float acc = 0.f;
#pragma unroll
        for (int i = 0; i < 3; i++)
#pragma unroll
        for (int j = 0; j < 3; j++)
            acc = fmaf(img[(y0 + dy + i) * 28 + x0 + dx + j], w[i * 3 + j], acc);
        m = fmaxf(m, fmaf(acc, s, bb));  // bn affine; relu commutes with max
    }
    g_h[(size_t)b * FEAT + t] = fmaxf(m, 0.f);
}

// ---------------- kernel 3: GEMM (f32x2) + exact radix top-k + binarize ----------------
#define SMEM_H    (FEAT * BM * 4)                 // 20480  (h tile, row-pair packed)
#define SMEM_Z    (BM * EMB * 4)                  // 131072 (z tile / keys)
#define SMEM_HIST (4 * 256 * 4)                   // 4096
#define SMEM_TOTAL (SMEM_H + SMEM_Z + SMEM_HIST + 32 + 64)

__global__ __launch_bounds__(256, 1) void gemm_select_kernel(float* __restrict__ out)
{
    extern __shared__ char smem[];
    ull*      sh_h2   = (ull*)smem;                                  // [FEAT][8] row pairs
    float*    sh_hf   = (float*)smem;                                // float view [FEAT][16]
    float*    sh_z    = (float*)(smem + SMEM_H);                     // [BM][EMB]
    unsigned* sh_zu   = (unsigned*)sh_z;
    int*      sh_hist = (int*)(smem + SMEM_H + SMEM_Z);              // [4][256]
    int*      sh_state= (int*)(smem + SMEM_H + SMEM_Z + SMEM_HIST);  // [4][2]
    unsigned* sh_thr  = (unsigned*)(sh_state + 8);                   // [16]

    int tid = threadIdx.x;
    int b0  = blockIdx.x * BM;

    // load h tile: sh_hf[k*16 + r] = h[b0+r][k]  (pairs (2rp,2rp+1) contiguous -> 64-bit LDS)
    for (int idx = tid; idx < BM * FEAT; idx += 256) {
        int r = idx / FEAT, k = idx - r * FEAT;
        sh_hf[k * BM + r] = g_h[(size_t)(b0 + r) * FEAT + k];
    }
    __syncthreads();

    // GEMM: each thread covers 4 columns x 16 rows (as 8 row-pairs) per 1024-col chunk
    for (int chunk = 0; chunk < 2; chunk++) {
        int jb = chunk * 1024 + tid;
        ull acc[8][4];
#pragma unroll
        for (int rp = 0; rp < 8; rp++)
#pragma unroll
            for (int c = 0; c < 4; c++) acc[rp][c] = 0ull;

        const float* wp = g_wT + jb;
        float cur[16];
#pragma unroll
        for (int kk = 0; kk < 4; kk++)
#pragma unroll
            for (int c = 0; c < 4; c++) cur[kk * 4 + c] = wp[kk * EMB + c * 256];

        for (int kq = 0; kq < 80; kq++) {
            const float* wn = wp + ((kq < 79) ? 4 * EMB : 0);   // prefetch next quad (clamped)
            float nxt[16];
#pragma unroll
            for (int kk = 0; kk < 4; kk++)
#pragma unroll
                for (int c = 0; c < 4; c++) nxt[kk * 4 + c] = wn[kk * EMB + c * 256];
#pragma unroll
            for (int kk = 0; kk < 4; kk++) {
                int k = kq * 4 + kk;
                ull w2[4];
#pragma unroll
                for (int c = 0; c < 4; c++) w2[c] = pack2(cur[kk * 4 + c], cur[kk * 4 + c]);
#pragma unroll
                for (int rp = 0; rp < 8; rp++) {
                    ull h2 = sh_h2[k * 8 + rp];     // broadcast LDS.64
#pragma unroll
                    for (int c = 0; c < 4; c++) fma2(acc[rp][c], h2, w2[c]);
                }
            }
#pragma unroll
            for (int i = 0; i < 16; i++) cur[i] = nxt[i];
            wp = wn;
        }
#pragma unroll
        for (int rp = 0; rp < 8; rp++)
#pragma unroll
            for (int c = 0; c < 4; c++) {
                float lo, hi; unpack2(acc[rp][c], lo, hi);
                int j = jb + c * 256;
                sh_z[(2 * rp) * EMB + j]     = lo;
                sh_z[(2 * rp + 1) * EMB + j] = hi;
            }
    }
    __syncthreads();

    // fp32 -> order-preserving uint32 keys, in place
    for (int idx = tid; idx < BM * EMB; idx += 256) {
        unsigned u = __float_as_uint(sh_z[idx]);
        u = (u & 0x80000000u) ? ~u : (u | 0x80000000u);
        sh_zu[idx] = u;
    }
    __syncthreads();

    // exact 103rd-largest per row: 4-pass MSB radix select, 4 rows in parallel (64 thr/row)
    int g  = tid >> 6;
    int gt = tid & 63;
    int* hist = sh_hist + g * 256;

    for (int round = 0; round < 4; round++) {
        int row = round * 4 + g;
        const unsigned* zr = sh_zu + row * EMB;
        int krem = KACT;
        unsigned prefix = 0, mask = 0;
        for (int pass = 0; pass < 4; pass++) {
            int shift = 24 - 8 * pass;
            for (int i = gt; i < 256; i += 64) hist[i] = 0;
            __syncthreads();
            for (int i = gt; i < EMB; i += 64) {
                unsigned u = zr[i];
                if ((u & mask) == prefix) atomicAdd(&hist[(u >> shift) & 255], 1);
            }
            __syncthreads();
            if (gt < 32) {                      // one full warp per group
                int l = gt;
                int s = 0;
#pragma unroll
                for (int k = 0; k < 8; k++) s += hist[255 - (l * 8 + k)];
                int cum = s;                     // descending inclusive scan
#pragma unroll
                for (int off = 1; off < 32; off <<= 1) {
                    int v = __shfl_up_sync(0xffffffffu, cum, off);
                    if (l >= off) cum += v;
                }
                unsigned ball = __ballot_sync(0xffffffffu, cum >= krem);
                int lstar = __ffs(ball) - 1;
                if (l == lstar) {
                    int c = cum - s;
                    int bsel = 0, nk = krem;
#pragma unroll
                    for (int k = 0; k < 8; k++) {
                        int b = 255 - (l * 8 + k);
                        int h = hist[b];
                        if (c + h >= krem) { bsel = b; nk = krem - c; break; }
                        c += h;
                    }
                    sh_state[g * 2]     = bsel;
                    sh_state[g * 2 + 1] = nk;
                }
            }
            __syncthreads();
            int bsel = sh_state[g * 2];
            krem = sh_state[g * 2 + 1];
            prefix |= ((unsigned)bsel) << shift;
            mask   |= 0xFFu << shift;
        }
        if (gt == 0) sh_thr[row] = prefix;      // exact key of 103rd largest
    }
    __syncthreads();

    // binarize: z >= thr  <=>  key >= thr_key (monotone map); includes ties like the reference
    float* outp = out + (size_t)b0 * EMB;
    for (int idx = tid; idx < BM * EMB; idx += 256) {
        int r = idx >> 11;
        outp[idx] = (sh_zu[idx] >= sh_thr[r]) ? 1.0f : 0.0f;
    }
}

extern "C" void kernel_launch(void* const* d_in, const int* in_sizes, int n_in,
                              void* d_out, int out_size)
{
    const float* x      = (const float*)d_in[0];
    const float* conv_w = (const float*)d_in[1];
    const float* gamma  = (const float*)d_in[2];
    const float* beta   = (const float*)d_in[3];
    const float* mean   = (const float*)d_in[4];
    const float* var    = (const float*)d_in[5];
    const float* fc_w   = (const float*)d_in[6];
    float* out = (float*)d_out;

    cudaFuncSetAttribute(gemm_select_kernel,
                         cudaFuncAttributeMaxDynamicSharedMemorySize, SMEM_TOTAL);

    transpose_w_kernel<<<(FEAT * EMB + 255) / 256, 256>>>(fc_w);
    conv_pool_kernel<<<BATCH, 320>>>(x, conv_w, gamma, beta, mean, var);
    gemm_select_kernel<<<BATCH / BM, 256, SMEM_TOTAL>>>(out);
}

// round 3
// speedup vs baseline: 1.4682x; 1.4682x over previous
#include <cuda_runtime.h>

#define BATCH 32768
#define EMB   2048
#define FEAT  320
#define KACT  103        // ceil(0.05 * 2048)
#define BM    16
#define NT    512

// scratch (no allocations allowed -> __device__ globals)
__device__ float g_h[BATCH * FEAT];     // pooled features, 42 MB
__device__ float g_wT[FEAT * EMB];      // fc_w transposed, 2.6 MB (L2-resident)

typedef unsigned long long ull;

__device__ __forceinline__ ull pack2(float x, float y) {
    ull r; asm("mov.b64 %0, {%1, %2};" : "=l"(r) : "f"(x), "f"(y)); return r;
}
__device__ __forceinline__ void unpack2(ull v, float& x, float& y) {
    asm("mov.b64 {%0, %1}, %2;" : "=f"(x), "=f"(y) : "l"(v));
}
// packed dual-fp32 FMA (Blackwell FFMA2: 2x scalar FFMA throughput, PTX-only path)
__device__ __forceinline__ void fma2(ull& acc, ull a, ull b) {
    asm("fma.rn.f32x2 %0, %1, %2, %0;" : "+l"(acc) : "l"(a), "l"(b));
}

// ---------------- kernel 1: conv + bn + relu + maxpool  (+ fused w-transpose) ----------------
__global__ __launch_bounds__(320) void conv_pool_kernel(
    const float* __restrict__ x, const float* __restrict__ conv_w,
    const float* __restrict__ gamma, const float* __restrict__ beta,
    const float* __restrict__ mean, const float* __restrict__ var,
    const float* __restrict__ fc_w)
{
    __shared__ float img[784];
    int b = blockIdx.x;

    // fused transpose: blocks 0..2047 each move 320 elements of fc_w -> g_wT
    if (b < (FEAT * EMB) / 320) {
        int idx = b * 320 + threadIdx.x;           // < 655360
        int k = idx >> 11, j = idx & 2047;         // idx = k*2048 + j
        g_wT[idx] = fc_w[j * FEAT + k];            // coalesced store
    }

    const float* xb = x + (size_t)b * 784;
    for (int i = threadIdx.x; i < 784; i += 320) img[i] = xb[i];

    int t = threadIdx.x;                // 320 threads = 320 pooled outputs
    int c = t >> 6, r = t & 63, py = r >> 3, px = r & 7;
    float w[9];
#pragma unroll
    for (int i = 0; i < 9; i++) w[i] = __ldg(&conv_w[c * 9 + i]);
    float s  = __ldg(&gamma[c]) / sqrtf(__ldg(&var[c]) + 1e-5f);
    float bb = __ldg(&beta[c]) - __ldg(&mean[c]) * s;
    __syncthreads();

    int y0 = py * 3, x0 = px * 3;
    float m = -3.402823466e38f;
#pragma unroll
    for (int dy = 0; dy < 3; dy++)
#pragma unroll
    for (int dx = 0; dx < 3; dx++) {
        float acc = 0.f;
#pragma unroll
        for (int i = 0; i < 3; i++)
#pragma unroll
        for (int j = 0; j < 3; j++)
            acc = fmaf(img[(y0 + dy + i) * 28 + x0 + dx + j], w[i * 3 + j], acc);
        m = fmaxf(m, fmaf(acc, s, bb));  // bn affine; relu commutes with max
    }
    g_h[(size_t)b * FEAT + t] = fmaxf(m, 0.f);
}

// ---------------- kernel 2: GEMM (f32x2) + exact radix top-k + binarize ----------------
#define SMEM_H    (FEAT * BM * 4)                 // 20480  (h tile, row-pair packed)
#define SMEM_Z    (BM * EMB * 4)                  // 131072 (z tile / keys)
#define SMEM_HIST (8 * 256 * 4)                   // 8192
#define SMEM_TOTAL (SMEM_H + SMEM_Z + SMEM_HIST + 64 + 64)

__global__ __launch_bounds__(NT, 1) void gemm_select_kernel(float* __restrict__ out)
{
    extern __shared__ char smem[];
    ull*      sh_h2   = (ull*)smem;                                  // [FEAT][8] row pairs
    float*    sh_hf   = (float*)smem;                                // float view [FEAT][16]
    float*    sh_z    = (float*)(smem + SMEM_H);                     // [BM][EMB]
    unsigned* sh_zu   = (unsigned*)sh_z;
    int*      sh_hist = (int*)(smem + SMEM_H + SMEM_Z);              // [8][256]
    int*      sh_state= (int*)(smem + SMEM_H + SMEM_Z + SMEM_HIST);  // [8][2]
    unsigned* sh_thr  = (unsigned*)(sh_state + 16);                  // [16]

    int tid = threadIdx.x;
    int b0  = blockIdx.x * BM;

    // load h tile: sh_hf[k*16 + r] = h[b0+r][k]  (pairs (2rp,2rp+1) contiguous -> LDS.128)
    for (int idx = tid; idx < BM * FEAT; idx += NT) {
        int r = idx / FEAT, k = idx - r * FEAT;
        sh_hf[k * BM + r] = g_h[(size_t)(b0 + r) * FEAT + k];
    }
    __syncthreads();

    // GEMM: each thread -> 4 consecutive columns x 16 rows (8 row-pairs)
    int j0 = tid * 4;
    ull acc[8][4];
#pragma unroll
    for (int rp = 0; rp < 8; rp++)
#pragma unroll
        for (int c = 0; c < 4; c++) acc[rp][c] = 0ull;

    const float* wb = g_wT + j0;
    float4 wv = *(const float4*)wb;                 // k=0 prefetch (one LDG.128)

#pragma unroll 2
    for (int k = 0; k < FEAT; k++) {
        int kn = (k < FEAT - 1) ? k + 1 : k;
        float4 wn = *(const float4*)(wb + kn * EMB);        // prefetch next k

        ull w2[4];
        w2[0] = pack2(wv.x, wv.x);
        w2[1] = pack2(wv.y, wv.y);
        w2[2] = pack2(wv.z, wv.z);
        w2[3] = pack2(wv.w, wv.w);

        const ulonglong2* hk = (const ulonglong2*)(sh_h2 + k * 8);
        ulonglong2 ha = hk[0];                               // rp0,1  (LDS.128 broadcast)
        ulonglong2 hb = hk[1];                               // rp2,3
        ulonglong2 hc = hk[2];                               // rp4,5
        ulonglong2 hd = hk[3];                               // rp6,7
#pragma unroll
        for (int c = 0; c < 4; c++) {
            fma2(acc[0][c], ha.x, w2[c]);
            fma2(acc[1][c], ha.y, w2[c]);
            fma2(acc[2][c], hb.x, w2[c]);
            fma2(acc[3][c], hb.y, w2[c]);
            fma2(acc[4][c], hc.x, w2[c]);
            fma2(acc[5][c], hc.y, w2[c]);
            fma2(acc[6][c], hd.x, w2[c]);
            fma2(acc[7][c], hd.y, w2[c]);
        }
        wv = wn;
    }

    // epilogue: unpack row pairs, STS.128 per row
#pragma unroll
    for (int rp = 0; rp < 8; rp++) {
        float4 lo4, hi4;
        unpack2(acc[rp][0], lo4.x, hi4.x);
        unpack2(acc[rp][1], lo4.y, hi4.y);
        unpack2(acc[rp][2], lo4.z, hi4.z);
        unpack2(acc[rp][3], lo4.w, hi4.w);
        *(float4*)&sh_z[(2 * rp) * EMB + j0]     = lo4;
        *(float4*)&sh_z[(2 * rp + 1) * EMB + j0] = hi4;
    }
    __syncthreads();

    // fp32 -> order-preserving uint32 keys, in place
    for (int idx = tid; idx < BM * EMB; idx += NT) {
        unsigned u = __float_as_uint(sh_z[idx]);
        u = (u & 0x80000000u) ? ~u : (u | 0x80000000u);
        sh_zu[idx] = u;
    }
    __syncthreads();

    // exact 103rd-largest per row: 4-pass MSB radix select, 8 rows in parallel (64 thr/row)
    int g  = tid >> 6;       // 0..7
    int gt = tid & 63;
    int* hist = sh_hist + g * 256;

    for (int round = 0; round < 2; round++) {
        int row = round * 8 + g;
        const unsigned* zr = sh_zu + row * EMB;
        int krem = KACT;
        unsigned prefix = 0, mask = 0;
        for (int pass = 0; pass < 4; pass++) {
            int shift = 24 - 8 * pass;
            for (int i = gt; i < 256; i += 64) hist[i] = 0;
            __syncthreads();
            for (int i = gt; i < EMB; i += 64) {
                unsigned u = zr[i];
                if ((u & mask) == prefix) atomicAdd(&hist[(u >> shift) & 255], 1);
            }
            __syncthreads();
            if (gt < 32) {                      // one full warp per group
                int l = gt;
                int s = 0;
#pragma unroll
                for (int k = 0; k < 8; k++) s += hist[255 - (l * 8 + k)];
                int cum = s;                     // descending inclusive scan
#pragma unroll
                for (int off = 1; off < 32; off <<= 1) {
                    int v = __shfl_up_sync(0xffffffffu, cum, off);
                    if (l >= off) cum += v;
                }
                unsigned ball = __ballot_sync(0xffffffffu, cum >= krem);
                int lstar = __ffs(ball) - 1;
                if (l == lstar) {
                    int c = cum - s;
                    int bsel = 0, nk = krem;
#pragma unroll
                    for (int k = 0; k < 8; k++) {
                        int b = 255 - (l * 8 + k);
                        int h = hist[b];
                        if (c + h >= krem) { bsel = b; nk = krem - c; break; }
                        c += h;
                    }
                    sh_state[g * 2]     = bsel;
                    sh_state[g * 2 + 1] = nk;
                }
            }
            __syncthreads();
            int bsel = sh_state[g * 2];
            krem = sh_state[g * 2 + 1];
            prefix |= ((unsigned)bsel) << shift;
            mask   |= 0xFFu << shift;
        }
        if (gt == 0) sh_thr[row] = prefix;      // exact key of 103rd largest
    }
    __syncthreads();

    // binarize: z >= thr  <=>  key >= thr_key (monotone map); includes ties like the reference
    float* outp = out + (size_t)b0 * EMB;
    for (int idx = tid; idx < BM * EMB; idx += NT) {
        int r = idx >> 11;
        outp[idx] = (sh_zu[idx] >= sh_thr[r]) ? 1.0f : 0.0f;
    }
}

extern "C" void kernel_launch(void* const* d_in, const int* in_sizes, int n_in,
                              void* d_out, int out_size)
{
    const float* x      = (const float*)d_in[0];
    const float* conv_w = (const float*)d_in[1];
    const float* gamma  = (const float*)d_in[2];
    const float* beta   = (const float*)d_in[3];
    const float* mean   = (const float*)d_in[4];
    const float* var    = (const float*)d_in[5];
    const float* fc_w   = (const float*)d_in[6];
    float* out = (float*)d_out;

    cudaFuncSetAttribute(gemm_select_kernel,
                         cudaFuncAttributeMaxDynamicSharedMemorySize, SMEM_TOTAL);

    conv_pool_kernel<<<BATCH, 320>>>(x, conv_w, gamma, beta, mean, var, fc_w);
    gemm_select_kernel<<<BATCH / BM, NT, SMEM_TOTAL>>>(out);
}